// round 13
// baseline (speedup 1.0000x reference)
#include <cuda_runtime.h>
#include <cuda_fp16.h>
#include <math.h>

#define NN 100000
#define EE 3200000
#define GG 1024
#define NREP 64   // stats replicas

// ---------------- scratch (no allocations allowed) ----------------
__device__ __half g_z16[NN * 64];     // fp16 gather operand (z of current layer)
__device__ float  g_u[NN * 64];       // u = relu(z+agg+b1), fp32
__device__ float  g_statsP[NREP * 128]; // replicated [sum(64), sumsq(64)]
__device__ float  g_W2p[64 * 64];
__device__ float  g_b2p[64];
__device__ int    g_cur[NN];          // degree counter
__device__ int    g_off[NN + 1];      // CSR offsets
__device__ int    g_col[EE];          // CSR column (src) list
__device__ int    g_rank[EE];         // per-edge rank within its dst bucket
__device__ int    g_arrive[2];        // last-block tickets (self-resetting)

struct alignas(8) H4 { __half2 a, b; };

__device__ __forceinline__ void red_add_v4(float* addr, float4 v) {
    asm volatile("red.global.add.v4.f32 [%0], {%1, %2, %3, %4};"
                 :: "l"(addr), "f"(v.x), "f"(v.y), "f"(v.z), "f"(v.w)
                 : "memory");
}
__device__ __forceinline__ void red_add_f(float* addr, float v) {
    asm volatile("red.global.add.f32 [%0], %1;" :: "l"(addr), "f"(v) : "memory");
}
__device__ __forceinline__ float4 h4_to_f4(H4 p) {
    float2 lo = __half22float2(p.a);
    float2 hi = __half22float2(p.b);
    return make_float4(lo.x, lo.y, hi.x, hi.y);
}

// ====== hist + rank capture: rank[e] = old count of dst[e] ======
__global__ __launch_bounds__(256) void hist_kernel(const int4* __restrict__ dst4) {
    int e = blockIdx.x * 256 + threadIdx.x;   // over EE/4
    if (e < EE / 4) {
        int4 d = __ldg(dst4 + e);
        int4 r;
        r.x = atomicAdd(&g_cur[d.x], 1);
        r.y = atomicAdd(&g_cur[d.y], 1);
        r.z = atomicAdd(&g_cur[d.z], 1);
        r.w = atomicAdd(&g_cur[d.w], 1);
        ((int4*)g_rank)[e] = r;
    }
}

// scan + zero statsP + zero xg + reset tickets
__global__ __launch_bounds__(1024) void scan_kernel(float* __restrict__ xg) {
    for (int i = threadIdx.x; i < NREP * 128; i += 1024) g_statsP[i] = 0.f;
    for (int i = threadIdx.x; i < GG * 64; i += 1024) xg[i] = 0.f;
    if (threadIdx.x < 2) g_arrive[threadIdx.x] = 0;

    __shared__ int part[1024];
    const int C = (NN + 1023) / 1024;   // 98
    const int t = threadIdx.x;
    const int begin = t * C;
    const int end = min(begin + C, NN);
    int s = 0;
    for (int i = begin; i < end; i++) s += g_cur[i];
    part[t] = s;
    __syncthreads();
    for (int d = 1; d < 1024; d <<= 1) {
        int v = (t >= d) ? part[t - d] : 0;
        __syncthreads();
        part[t] += v;
        __syncthreads();
    }
    int run = (t == 0) ? 0 : part[t - 1];
    for (int i = begin; i < end; i++) {
        int d = g_cur[i];
        g_off[i] = run;
        run += d;
    }
    if (t == 1023) g_off[NN] = run;
}

// ---------------- gemm0 (z16 = X @ W1_0, fp16 out) + scatter tail ----------------
__global__ __launch_bounds__(256, 4) void gemm0_scatter(const float* __restrict__ X,
                                                        const float* __restrict__ W,
                                                        __half* __restrict__ out16, int n,
                                                        const int4* __restrict__ src4,
                                                        const int4* __restrict__ dst4) {
    __shared__ float Xs[64][68];
    __shared__ float Ws[64][64];
    const int tid  = threadIdx.x;
    const int row0 = blockIdx.x * 64;
    const int col4 = (tid & 15) * 4;
    const int row4 = (tid >> 4) * 4;

    float acc[4][4];
#pragma unroll
    for (int r = 0; r < 4; r++)
#pragma unroll
        for (int c = 0; c < 4; c++) acc[r][c] = 0.f;

    for (int k0 = 0; k0 < 128; k0 += 64) {
#pragma unroll
        for (int t = 0; t < 4; t++) {
            int fidx = t * 256 + tid;
            int r = fidx >> 4;
            int c = (fidx & 15) * 4;
            float4 v = make_float4(0.f, 0.f, 0.f, 0.f);
            int row = row0 + r;
            if (row < n) v = *(const float4*)(X + (size_t)row * 128 + k0 + c);
            *(float4*)&Xs[r][c] = v;
        }
#pragma unroll
        for (int t = 0; t < 4; t++) {
            int fidx = t * 256 + tid;
            int kk = fidx >> 4;
            int c = (fidx & 15) * 4;
            *(float4*)&Ws[kk][c] = *(const float4*)(W + (size_t)(k0 + kk) * 64 + c);
        }
        __syncthreads();
#pragma unroll
        for (int kk = 0; kk < 64; kk += 4) {
            float4 wv0 = *(float4*)&Ws[kk + 0][col4];
            float4 wv1 = *(float4*)&Ws[kk + 1][col4];
            float4 wv2 = *(float4*)&Ws[kk + 2][col4];
            float4 wv3 = *(float4*)&Ws[kk + 3][col4];
#pragma unroll
            for (int r = 0; r < 4; r++) {
                float4 xv = *(float4*)&Xs[row4 + r][kk];
                acc[r][0] += xv.x * wv0.x + xv.y * wv1.x + xv.z * wv2.x + xv.w * wv3.x;
                acc[r][1] += xv.x * wv0.y + xv.y * wv1.y + xv.z * wv2.y + xv.w * wv3.y;
                acc[r][2] += xv.x * wv0.z + xv.y * wv1.z + xv.z * wv2.z + xv.w * wv3.z;
                acc[r][3] += xv.x * wv0.w + xv.y * wv1.w + xv.z * wv2.w + xv.w * wv3.w;
            }
        }
        __syncthreads();
    }
#pragma unroll
    for (int r = 0; r < 4; r++) {
        int row = row0 + row4 + r;
        if (row < n) {
            H4 p;
            p.a = __floats2half2_rn(acc[r][0], acc[r][1]);
            p.b = __floats2half2_rn(acc[r][2], acc[r][3]);
            *(H4*)(out16 + (size_t)row * 64 + col4) = p;
        }
    }

    // ---- scatter tail: this block handles 512 int4-edges, atomic-free ----
#pragma unroll
    for (int t = 0; t < 2; t++) {
        int e = blockIdx.x * 512 + t * 256 + tid;
        if (e < EE / 4) {
            int4 s = __ldg(src4 + e);
            int4 d = __ldg(dst4 + e);
            int4 r = __ldg(((const int4*)g_rank) + e);
            g_col[__ldg(&g_off[d.x]) + r.x] = s.x;
            g_col[__ldg(&g_off[d.y]) + r.y] = s.y;
            g_col[__ldg(&g_off[d.z]) + r.z] = s.z;
            g_col[__ldg(&g_off[d.w]) + r.w] = s.w;
        }
    }
}

// ========== fused gather(fp16) + self + bias + relu + stats + last-block BN fold ==========
__global__ __launch_bounds__(256, 8) void gather_post(const __half* __restrict__ z16,
                                                      const float* __restrict__ b1,
                                                      float* __restrict__ u,
                                                      const float* __restrict__ W2,
                                                      const float* __restrict__ b2,
                                                      const float* __restrict__ gam,
                                                      const float* __restrict__ be,
                                                      int slot) {
    __shared__ float ssum[8][64];
    __shared__ float ssq[8][64];
    __shared__ int isLast;
    const int warp = threadIdx.x >> 5;
    const int lane = threadIdx.x & 31;
    const int n = blockIdx.x * 8 + warp;
    const int half = lane >> 4;           // 0 or 1
    const int c4 = (lane & 15) * 4;       // feature offset (halves)

    const int beg = __ldg(&g_off[n]);
    const int endo = __ldg(&g_off[n + 1]);

    float4 acc = make_float4(0.f, 0.f, 0.f, 0.f);
    int j = beg + half;
    for (; j + 6 < endo; j += 8) {
        int s0 = __ldg(&g_col[j]);
        int s1 = __ldg(&g_col[j + 2]);
        int s2 = __ldg(&g_col[j + 4]);
        int s3 = __ldg(&g_col[j + 6]);
        float4 v0 = h4_to_f4(*(const H4*)(z16 + (size_t)s0 * 64 + c4));
        float4 v1 = h4_to_f4(*(const H4*)(z16 + (size_t)s1 * 64 + c4));
        float4 v2 = h4_to_f4(*(const H4*)(z16 + (size_t)s2 * 64 + c4));
        float4 v3 = h4_to_f4(*(const H4*)(z16 + (size_t)s3 * 64 + c4));
        acc.x += (v0.x + v1.x) + (v2.x + v3.x);
        acc.y += (v0.y + v1.y) + (v2.y + v3.y);
        acc.z += (v0.z + v1.z) + (v2.z + v3.z);
        acc.w += (v0.w + v1.w) + (v2.w + v3.w);
    }
#pragma unroll 1
    for (; j < endo; j += 2) {
        int s0 = __ldg(&g_col[j]);
        float4 v0 = h4_to_f4(*(const H4*)(z16 + (size_t)s0 * 64 + c4));
        acc.x += v0.x; acc.y += v0.y; acc.z += v0.z; acc.w += v0.w;
    }
    acc.x += __shfl_down_sync(0xffffffffu, acc.x, 16);
    acc.y += __shfl_down_sync(0xffffffffu, acc.y, 16);
    acc.z += __shfl_down_sync(0xffffffffu, acc.z, 16);
    acc.w += __shfl_down_sync(0xffffffffu, acc.w, 16);

    if (half == 0) {
        float4 zz = h4_to_f4(*(const H4*)(z16 + (size_t)n * 64 + c4));
        float4 bb = *(const float4*)(b1 + c4);
        float4 o;
        o.x = fmaxf(zz.x + acc.x + bb.x, 0.f);
        o.y = fmaxf(zz.y + acc.y + bb.y, 0.f);
        o.z = fmaxf(zz.z + acc.z + bb.z, 0.f);
        o.w = fmaxf(zz.w + acc.w + bb.w, 0.f);
        *(float4*)(u + (size_t)n * 64 + c4) = o;
        *(float4*)&ssum[warp][c4] = o;
        float4 q = make_float4(o.x * o.x, o.y * o.y, o.z * o.z, o.w * o.w);
        *(float4*)&ssq[warp][c4] = q;
    }
    __syncthreads();
    const int tid = threadIdx.x;
    const int rep = blockIdx.x & (NREP - 1);
    if (tid < 64) {
        float s = 0.f;
#pragma unroll
        for (int w = 0; w < 8; w++) s += ssum[w][tid];
        red_add_f(&g_statsP[rep * 128 + tid], s);
    } else if (tid < 128) {
        int f = tid - 64;
        float s = 0.f;
#pragma unroll
        for (int w = 0; w < 8; w++) s += ssq[w][f];
        red_add_f(&g_statsP[rep * 128 + 64 + f], s);
    }

    // ---- last-block BN fold (threadFenceReduction pattern) ----
    __threadfence();
    __syncthreads();
    if (tid == 0) {
        int c = atomicAdd(&g_arrive[slot], 1);
        isLast = (c == (int)gridDim.x - 1);
    }
    __syncthreads();
    if (!isLast) return;
    __threadfence();

    float* scale = &ssum[0][0];
    float* shift = &ssum[1][0];
    float (*pa)[64] = (float (*)[64])&ssq[0][0];
    const int jj = tid & 63;
    const int q = tid >> 6;
    if (q == 0) {
        float sum = 0.f, sq = 0.f;
#pragma unroll 8
        for (int r = 0; r < NREP; r++) {
            sum += g_statsP[r * 128 + jj];
            sq  += g_statsP[r * 128 + 64 + jj];
        }
        const float inv_n = 1.0f / (float)NN;
        float mu = sum * inv_n;
        float var = sq * inv_n - mu * mu;
        float sc = gam[jj] * rsqrtf(var + 1e-5f);
        scale[jj] = sc;
        shift[jj] = be[jj] - mu * sc;
    }
    __syncthreads();
    float facc = 0.f;
#pragma unroll
    for (int t = 0; t < 16; t++) {
        int k = q * 16 + t;
        float w = W2[k * 64 + jj];
        g_W2p[k * 64 + jj] = scale[k] * w;
        facc += shift[k] * w;
    }
    pa[q][jj] = facc;
    // re-zero statsP for the next gather + reset ticket
    for (int i = tid; i < NREP * 128; i += 256) g_statsP[i] = 0.f;
    __syncthreads();
    if (q == 0) g_b2p[jj] = b2[jj] + pa[0][jj] + pa[1][jj] + pa[2][jj] + pa[3][jj];
    if (tid == 0) g_arrive[slot] = 0;
}

// ---------------- GEMM: out[n,64] = X[n,K] @ W[K,64] (final: bias+relu+pool) ----------------
template <int K, bool RELU, bool BIAS, bool POOL, bool OUT16>
__global__ __launch_bounds__(256, 4) void gemm64(const float* __restrict__ X,
                                                 const float* __restrict__ W,
                                                 const float* __restrict__ bias,
                                                 float* __restrict__ out,
                                                 __half* __restrict__ out16, int n,
                                                 const int* __restrict__ batch,
                                                 float* __restrict__ xg) {
    __shared__ float Xs[64][68];
    __shared__ float Ws[64][64];
    const int tid  = threadIdx.x;
    const int row0 = blockIdx.x * 64;
    const int col4 = (tid & 15) * 4;
    const int row4 = (tid >> 4) * 4;

    float acc[4][4];
#pragma unroll
    for (int r = 0; r < 4; r++)
#pragma unroll
        for (int c = 0; c < 4; c++) acc[r][c] = 0.f;

    for (int k0 = 0; k0 < K; k0 += 64) {
#pragma unroll
        for (int t = 0; t < 4; t++) {
            int fidx = t * 256 + tid;
            int r = fidx >> 4;
            int c = (fidx & 15) * 4;
            float4 v = make_float4(0.f, 0.f, 0.f, 0.f);
            int row = row0 + r;
            if (row < n) v = *(const float4*)(X + (size_t)row * K + k0 + c);
            *(float4*)&Xs[r][c] = v;
        }
#pragma unroll
        for (int t = 0; t < 4; t++) {
            int fidx = t * 256 + tid;
            int kk = fidx >> 4;
            int c = (fidx & 15) * 4;
            *(float4*)&Ws[kk][c] = *(const float4*)(W + (size_t)(k0 + kk) * 64 + c);
        }
        __syncthreads();
#pragma unroll
        for (int kk = 0; kk < 64; kk += 4) {
            float4 wv0 = *(float4*)&Ws[kk + 0][col4];
            float4 wv1 = *(float4*)&Ws[kk + 1][col4];
            float4 wv2 = *(float4*)&Ws[kk + 2][col4];
            float4 wv3 = *(float4*)&Ws[kk + 3][col4];
#pragma unroll
            for (int r = 0; r < 4; r++) {
                float4 xv = *(float4*)&Xs[row4 + r][kk];
                acc[r][0] += xv.x * wv0.x + xv.y * wv1.x + xv.z * wv2.x + xv.w * wv3.x;
                acc[r][1] += xv.x * wv0.y + xv.y * wv1.y + xv.z * wv2.y + xv.w * wv3.y;
                acc[r][2] += xv.x * wv0.z + xv.y * wv1.z + xv.z * wv2.z + xv.w * wv3.z;
                acc[r][3] += xv.x * wv0.w + xv.y * wv1.w + xv.z * wv2.w + xv.w * wv3.w;
            }
        }
        __syncthreads();
    }
#pragma unroll
    for (int r = 0; r < 4; r++) {
        int row = row0 + row4 + r;
        if (row < n) {
            float4 o = make_float4(acc[r][0], acc[r][1], acc[r][2], acc[r][3]);
            if (BIAS) {
                o.x += bias[col4 + 0]; o.y += bias[col4 + 1];
                o.z += bias[col4 + 2]; o.w += bias[col4 + 3];
            }
            if (RELU) {
                o.x = fmaxf(o.x, 0.f); o.y = fmaxf(o.y, 0.f);
                o.z = fmaxf(o.z, 0.f); o.w = fmaxf(o.w, 0.f);
            }
            if (OUT16) {
                H4 p;
                p.a = __floats2half2_rn(o.x, o.y);
                p.b = __floats2half2_rn(o.z, o.w);
                *(H4*)(out16 + (size_t)row * 64 + col4) = p;
            } else {
                *(float4*)(out + (size_t)row * 64 + col4) = o;
                if (POOL) {
                    int b = __ldg(batch + row);
                    red_add_v4(xg + (size_t)b * 64 + col4, o);
                }
            }
        }
    }
}

// --------- fused middle: z' = relu(U @ W2p + b2p) @ W1_1 -> fp16 ---------
__global__ __launch_bounds__(256, 4) void gemm_mid(const float* __restrict__ U,
                                                   const float* __restrict__ W2p,
                                                   const float* __restrict__ b2p,
                                                   const float* __restrict__ W1_1,
                                                   __half* __restrict__ out16, int n) {
    __shared__ float Xs[64][68];
    __shared__ float Ws[64][64];
    const int tid  = threadIdx.x;
    const int row0 = blockIdx.x * 64;
    const int col4 = (tid & 15) * 4;
    const int row4 = (tid >> 4) * 4;

    float acc[4][4];
#pragma unroll
    for (int r = 0; r < 4; r++)
#pragma unroll
        for (int c = 0; c < 4; c++) acc[r][c] = 0.f;

#pragma unroll
    for (int t = 0; t < 4; t++) {
        int fidx = t * 256 + tid;
        int r = fidx >> 4;
        int c = (fidx & 15) * 4;
        float4 v = make_float4(0.f, 0.f, 0.f, 0.f);
        int row = row0 + r;
        if (row < n) v = *(const float4*)(U + (size_t)row * 64 + c);
        *(float4*)&Xs[r][c] = v;
        *(float4*)&Ws[r][c] = *(const float4*)(W2p + (size_t)r * 64 + c);
    }
    __syncthreads();
#pragma unroll
    for (int kk = 0; kk < 64; kk += 4) {
        float4 wv0 = *(float4*)&Ws[kk + 0][col4];
        float4 wv1 = *(float4*)&Ws[kk + 1][col4];
        float4 wv2 = *(float4*)&Ws[kk + 2][col4];
        float4 wv3 = *(float4*)&Ws[kk + 3][col4];
#pragma unroll
        for (int r = 0; r < 4; r++) {
            float4 xv = *(float4*)&Xs[row4 + r][kk];
            acc[r][0] += xv.x * wv0.x + xv.y * wv1.x + xv.z * wv2.x + xv.w * wv3.x;
            acc[r][1] += xv.x * wv0.y + xv.y * wv1.y + xv.z * wv2.y + xv.w * wv3.y;
            acc[r][2] += xv.x * wv0.z + xv.y * wv1.z + xv.z * wv2.z + xv.w * wv3.z;
            acc[r][3] += xv.x * wv0.w + xv.y * wv1.w + xv.z * wv2.w + xv.w * wv3.w;
        }
    }
    __syncthreads();

    float4 bb = *(const float4*)(b2p + col4);
#pragma unroll
    for (int r = 0; r < 4; r++) {
        float4 h;
        h.x = fmaxf(acc[r][0] + bb.x, 0.f);
        h.y = fmaxf(acc[r][1] + bb.y, 0.f);
        h.z = fmaxf(acc[r][2] + bb.z, 0.f);
        h.w = fmaxf(acc[r][3] + bb.w, 0.f);
        *(float4*)&Xs[row4 + r][col4] = h;
        acc[r][0] = acc[r][1] = acc[r][2] = acc[r][3] = 0.f;
    }
#pragma unroll
    for (int t = 0; t < 4; t++) {
        int fidx = t * 256 + tid;
        int kk = fidx >> 4;
        int c = (fidx & 15) * 4;
        *(float4*)&Ws[kk][c] = *(const float4*)(W1_1 + (size_t)kk * 64 + c);
    }
    __syncthreads();
#pragma unroll
    for (int kk = 0; kk < 64; kk += 4) {
        float4 wv0 = *(float4*)&Ws[kk + 0][col4];
        float4 wv1 = *(float4*)&Ws[kk + 1][col4];
        float4 wv2 = *(float4*)&Ws[kk + 2][col4];
        float4 wv3 = *(float4*)&Ws[kk + 3][col4];
#pragma unroll
        for (int r = 0; r < 4; r++) {
            float4 xv = *(float4*)&Xs[row4 + r][kk];
            acc[r][0] += xv.x * wv0.x + xv.y * wv1.x + xv.z * wv2.x + xv.w * wv3.x;
            acc[r][1] += xv.x * wv0.y + xv.y * wv1.y + xv.z * wv2.y + xv.w * wv3.y;
            acc[r][2] += xv.x * wv0.z + xv.y * wv1.z + xv.z * wv2.z + xv.w * wv3.z;
            acc[r][3] += xv.x * wv0.w + xv.y * wv1.w + xv.z * wv2.w + xv.w * wv3.w;
        }
    }
#pragma unroll
    for (int r = 0; r < 4; r++) {
        int row = row0 + row4 + r;
        if (row < n) {
            H4 p;
            p.a = __floats2half2_rn(acc[r][0], acc[r][1]);
            p.b = __floats2half2_rn(acc[r][2], acc[r][3]);
            *(H4*)(out16 + (size_t)row * 64 + col4) = p;
        }
    }
}

extern "C" void kernel_launch(void* const* d_in, const int* in_sizes, int n_in,
                              void* d_out, int out_size) {
    const float* x     = (const float*)d_in[0];
    const int*   ei    = (const int*)d_in[1];
    const int*   batch = (const int*)d_in[2];
    const float* W1_0  = (const float*)d_in[3];
    const float* b1_0  = (const float*)d_in[4];
    const float* g_0   = (const float*)d_in[5];
    const float* be_0  = (const float*)d_in[6];
    const float* W2_0  = (const float*)d_in[7];
    const float* b2_0  = (const float*)d_in[8];
    const float* W1_1  = (const float*)d_in[9];
    const float* b1_1  = (const float*)d_in[10];
    const float* g_1   = (const float*)d_in[11];
    const float* be_1  = (const float*)d_in[12];
    const float* W2_1  = (const float*)d_in[13];
    const float* b2_1  = (const float*)d_in[14];

    const int4* src4 = (const int4*)ei;
    const int4* dst4 = (const int4*)(ei + EE);

    __half* z16;
    float *u, *W2p, *b2p;
    int *cur;
    cudaGetSymbolAddress((void**)&z16, g_z16);
    cudaGetSymbolAddress((void**)&u, g_u);
    cudaGetSymbolAddress((void**)&W2p, g_W2p);
    cudaGetSymbolAddress((void**)&b2p, g_b2p);
    cudaGetSymbolAddress((void**)&cur, g_cur);

    float* out  = (float*)d_out;
    float* xg   = out;            // (G, 64)
    float* hout = out + GG * 64;  // (N, 64)

    const int gemm_blocks  = (NN + 63) / 64;   // 1563
    const int edge4_blocks = (EE / 4 + 255) / 256;
    const int node_blocks  = NN / 8;           // 12500

    // ---------- CSR build ----------
    cudaMemsetAsync(cur, 0, NN * sizeof(int));
    hist_kernel<<<edge4_blocks, 256>>>(dst4);
    scan_kernel<<<1, 1024>>>(xg);                     // + zero statsP, xg, tickets

    // ---------- layer 0 (gemm0 carries the scatter tail) ----------
    gemm0_scatter<<<gemm_blocks, 256>>>(x, W1_0, z16, NN, src4, dst4);
    gather_post<<<node_blocks, 256>>>(z16, b1_0, u, W2_0, b2_0, g_0, be_0, 0);
    gemm_mid<<<gemm_blocks, 256>>>(u, W2p, b2p, W1_1, z16, NN);

    // ---------- layer 1 ----------
    gather_post<<<node_blocks, 256>>>(z16, b1_1, u, W2_1, b2_1, g_1, be_1, 1);
    gemm64<64, true, true, true, false><<<gemm_blocks, 256>>>(
        u, W2p, b2p, hout, nullptr, NN, batch, xg);
}

// round 14
// speedup vs baseline: 1.0729x; 1.0729x over previous
#include <cuda_runtime.h>
#include <cuda_fp16.h>
#include <math.h>

#define NN 100000
#define EE 3200000
#define GG 1024
#define NREP 64   // stats replicas

// ---------------- scratch (no allocations allowed) ----------------
__device__ __half g_z16[NN * 64];     // fp16 gather operand (z of current layer)
__device__ float  g_u[NN * 64];       // u = relu(z+agg+b1), fp32
__device__ float  g_statsP[NREP * 128]; // replicated [sum(64), sumsq(64)]
__device__ float  g_W2p[64 * 64];
__device__ float  g_b2p[64];
__device__ int    g_cur[NN];          // degree counter
__device__ int    g_off[NN + 1];      // CSR offsets
__device__ int    g_col[EE];          // CSR column (src) list
__device__ int    g_rank[EE];         // per-edge rank within its dst bucket

struct alignas(8) H4 { __half2 a, b; };

__device__ __forceinline__ void red_add_v4(float* addr, float4 v) {
    asm volatile("red.global.add.v4.f32 [%0], {%1, %2, %3, %4};"
                 :: "l"(addr), "f"(v.x), "f"(v.y), "f"(v.z), "f"(v.w)
                 : "memory");
}
__device__ __forceinline__ void red_add_f(float* addr, float v) {
    asm volatile("red.global.add.f32 [%0], %1;" :: "l"(addr), "f"(v) : "memory");
}
__device__ __forceinline__ float4 h4_to_f4(H4 p) {
    float2 lo = __half22float2(p.a);
    float2 hi = __half22float2(p.b);
    return make_float4(lo.x, lo.y, hi.x, hi.y);
}

// ====== hist + rank capture: rank[e] = old count of dst[e] ======
__global__ __launch_bounds__(256) void hist_kernel(const int4* __restrict__ dst4) {
    int e = blockIdx.x * 256 + threadIdx.x;   // over EE/4
    if (e < EE / 4) {
        int4 d = __ldg(dst4 + e);
        int4 r;
        r.x = atomicAdd(&g_cur[d.x], 1);
        r.y = atomicAdd(&g_cur[d.y], 1);
        r.z = atomicAdd(&g_cur[d.z], 1);
        r.w = atomicAdd(&g_cur[d.w], 1);
        ((int4*)g_rank)[e] = r;
    }
}

// scan + zero statsP + zero xg (absorbs memset nodes)
__global__ __launch_bounds__(1024) void scan_kernel(float* __restrict__ xg) {
    for (int i = threadIdx.x; i < NREP * 128; i += 1024) g_statsP[i] = 0.f;
    for (int i = threadIdx.x; i < GG * 64; i += 1024) xg[i] = 0.f;

    __shared__ int part[1024];
    const int C = (NN + 1023) / 1024;   // 98
    const int t = threadIdx.x;
    const int begin = t * C;
    const int end = min(begin + C, NN);
    int s = 0;
    for (int i = begin; i < end; i++) s += g_cur[i];
    part[t] = s;
    __syncthreads();
    for (int d = 1; d < 1024; d <<= 1) {
        int v = (t >= d) ? part[t - d] : 0;
        __syncthreads();
        part[t] += v;
        __syncthreads();
    }
    int run = (t == 0) ? 0 : part[t - 1];
    for (int i = begin; i < end; i++) {
        int d = g_cur[i];
        g_off[i] = run;
        run += d;
    }
    if (t == 1023) g_off[NN] = run;
}

// ---------------- gemm0 (z16 = X @ W1_0, fp16 out) + atomic-free scatter tail ----------------
__global__ __launch_bounds__(256, 4) void gemm0_scatter(const float* __restrict__ X,
                                                        const float* __restrict__ W,
                                                        __half* __restrict__ out16, int n,
                                                        const int4* __restrict__ src4,
                                                        const int4* __restrict__ dst4) {
    __shared__ float Xs[64][68];
    __shared__ float Ws[64][64];
    const int tid  = threadIdx.x;
    const int row0 = blockIdx.x * 64;
    const int col4 = (tid & 15) * 4;
    const int row4 = (tid >> 4) * 4;

    float acc[4][4];
#pragma unroll
    for (int r = 0; r < 4; r++)
#pragma unroll
        for (int c = 0; c < 4; c++) acc[r][c] = 0.f;

    for (int k0 = 0; k0 < 128; k0 += 64) {
#pragma unroll
        for (int t = 0; t < 4; t++) {
            int fidx = t * 256 + tid;
            int r = fidx >> 4;
            int c = (fidx & 15) * 4;
            float4 v = make_float4(0.f, 0.f, 0.f, 0.f);
            int row = row0 + r;
            if (row < n) v = *(const float4*)(X + (size_t)row * 128 + k0 + c);
            *(float4*)&Xs[r][c] = v;
        }
#pragma unroll
        for (int t = 0; t < 4; t++) {
            int fidx = t * 256 + tid;
            int kk = fidx >> 4;
            int c = (fidx & 15) * 4;
            *(float4*)&Ws[kk][c] = *(const float4*)(W + (size_t)(k0 + kk) * 64 + c);
        }
        __syncthreads();
#pragma unroll
        for (int kk = 0; kk < 64; kk += 4) {
            float4 wv0 = *(float4*)&Ws[kk + 0][col4];
            float4 wv1 = *(float4*)&Ws[kk + 1][col4];
            float4 wv2 = *(float4*)&Ws[kk + 2][col4];
            float4 wv3 = *(float4*)&Ws[kk + 3][col4];
#pragma unroll
            for (int r = 0; r < 4; r++) {
                float4 xv = *(float4*)&Xs[row4 + r][kk];
                acc[r][0] += xv.x * wv0.x + xv.y * wv1.x + xv.z * wv2.x + xv.w * wv3.x;
                acc[r][1] += xv.x * wv0.y + xv.y * wv1.y + xv.z * wv2.y + xv.w * wv3.y;
                acc[r][2] += xv.x * wv0.z + xv.y * wv1.z + xv.z * wv2.z + xv.w * wv3.z;
                acc[r][3] += xv.x * wv0.w + xv.y * wv1.w + xv.z * wv2.w + xv.w * wv3.w;
            }
        }
        __syncthreads();
    }
#pragma unroll
    for (int r = 0; r < 4; r++) {
        int row = row0 + row4 + r;
        if (row < n) {
            H4 p;
            p.a = __floats2half2_rn(acc[r][0], acc[r][1]);
            p.b = __floats2half2_rn(acc[r][2], acc[r][3]);
            *(H4*)(out16 + (size_t)row * 64 + col4) = p;
        }
    }

    // ---- scatter tail: this block handles 512 int4-edges, atomic-free ----
#pragma unroll
    for (int t = 0; t < 2; t++) {
        int e = blockIdx.x * 512 + t * 256 + tid;
        if (e < EE / 4) {
            int4 s = __ldg(src4 + e);
            int4 d = __ldg(dst4 + e);
            int4 r = __ldg(((const int4*)g_rank) + e);
            g_col[__ldg(&g_off[d.x]) + r.x] = s.x;
            g_col[__ldg(&g_off[d.y]) + r.y] = s.y;
            g_col[__ldg(&g_off[d.z]) + r.z] = s.z;
            g_col[__ldg(&g_off[d.w]) + r.w] = s.w;
        }
    }
}

// ========== fused gather(fp16) + self + bias + relu + stats ==========
// one warp per node; 8 nodes per 256-thread block.
__global__ __launch_bounds__(256) void gather_post(const __half* __restrict__ z16,
                                                   const float* __restrict__ b1,
                                                   float* __restrict__ u) {
    __shared__ float ssum[8][64];
    __shared__ float ssq[8][64];
    const int warp = threadIdx.x >> 5;
    const int lane = threadIdx.x & 31;
    const int n = blockIdx.x * 8 + warp;
    const int half = lane >> 4;           // 0 or 1
    const int c4 = (lane & 15) * 4;       // feature offset (halves)

    const int beg = __ldg(&g_off[n]);
    const int endo = __ldg(&g_off[n + 1]);

    float4 acc = make_float4(0.f, 0.f, 0.f, 0.f);
    int j = beg + half;
    for (; j + 6 < endo; j += 8) {
        int s0 = __ldg(&g_col[j]);
        int s1 = __ldg(&g_col[j + 2]);
        int s2 = __ldg(&g_col[j + 4]);
        int s3 = __ldg(&g_col[j + 6]);
        float4 v0 = h4_to_f4(*(const H4*)(z16 + (size_t)s0 * 64 + c4));
        float4 v1 = h4_to_f4(*(const H4*)(z16 + (size_t)s1 * 64 + c4));
        float4 v2 = h4_to_f4(*(const H4*)(z16 + (size_t)s2 * 64 + c4));
        float4 v3 = h4_to_f4(*(const H4*)(z16 + (size_t)s3 * 64 + c4));
        acc.x += (v0.x + v1.x) + (v2.x + v3.x);
        acc.y += (v0.y + v1.y) + (v2.y + v3.y);
        acc.z += (v0.z + v1.z) + (v2.z + v3.z);
        acc.w += (v0.w + v1.w) + (v2.w + v3.w);
    }
#pragma unroll 1
    for (; j < endo; j += 2) {
        int s0 = __ldg(&g_col[j]);
        float4 v0 = h4_to_f4(*(const H4*)(z16 + (size_t)s0 * 64 + c4));
        acc.x += v0.x; acc.y += v0.y; acc.z += v0.z; acc.w += v0.w;
    }
    acc.x += __shfl_down_sync(0xffffffffu, acc.x, 16);
    acc.y += __shfl_down_sync(0xffffffffu, acc.y, 16);
    acc.z += __shfl_down_sync(0xffffffffu, acc.z, 16);
    acc.w += __shfl_down_sync(0xffffffffu, acc.w, 16);

    if (half == 0) {
        float4 zz = h4_to_f4(*(const H4*)(z16 + (size_t)n * 64 + c4));
        float4 bb = *(const float4*)(b1 + c4);
        float4 o;
        o.x = fmaxf(zz.x + acc.x + bb.x, 0.f);
        o.y = fmaxf(zz.y + acc.y + bb.y, 0.f);
        o.z = fmaxf(zz.z + acc.z + bb.z, 0.f);
        o.w = fmaxf(zz.w + acc.w + bb.w, 0.f);
        *(float4*)(u + (size_t)n * 64 + c4) = o;
        *(float4*)&ssum[warp][c4] = o;
        float4 q = make_float4(o.x * o.x, o.y * o.y, o.z * o.z, o.w * o.w);
        *(float4*)&ssq[warp][c4] = q;
    }
    __syncthreads();
    const int tid = threadIdx.x;
    const int rep = blockIdx.x & (NREP - 1);
    if (tid < 64) {
        float s = 0.f;
#pragma unroll
        for (int w = 0; w < 8; w++) s += ssum[w][tid];
        red_add_f(&g_statsP[rep * 128 + tid], s);
    } else if (tid < 128) {
        int f = tid - 64;
        float s = 0.f;
#pragma unroll
        for (int w = 0; w < 8; w++) s += ssq[w][f];
        red_add_f(&g_statsP[rep * 128 + 64 + f], s);
    }
}

// ---------------- GEMM: out[n,64] = X[n,K] @ W[K,64] (final: bias+relu+pool) ----------------
template <int K, bool RELU, bool BIAS, bool POOL, bool OUT16>
__global__ __launch_bounds__(256, 4) void gemm64(const float* __restrict__ X,
                                                 const float* __restrict__ W,
                                                 const float* __restrict__ bias,
                                                 float* __restrict__ out,
                                                 __half* __restrict__ out16, int n,
                                                 const int* __restrict__ batch,
                                                 float* __restrict__ xg) {
    __shared__ float Xs[64][68];
    __shared__ float Ws[64][64];
    const int tid  = threadIdx.x;
    const int row0 = blockIdx.x * 64;
    const int col4 = (tid & 15) * 4;
    const int row4 = (tid >> 4) * 4;

    float acc[4][4];
#pragma unroll
    for (int r = 0; r < 4; r++)
#pragma unroll
        for (int c = 0; c < 4; c++) acc[r][c] = 0.f;

    for (int k0 = 0; k0 < K; k0 += 64) {
#pragma unroll
        for (int t = 0; t < 4; t++) {
            int fidx = t * 256 + tid;
            int r = fidx >> 4;
            int c = (fidx & 15) * 4;
            float4 v = make_float4(0.f, 0.f, 0.f, 0.f);
            int row = row0 + r;
            if (row < n) v = *(const float4*)(X + (size_t)row * K + k0 + c);
            *(float4*)&Xs[r][c] = v;
        }
#pragma unroll
        for (int t = 0; t < 4; t++) {
            int fidx = t * 256 + tid;
            int kk = fidx >> 4;
            int c = (fidx & 15) * 4;
            *(float4*)&Ws[kk][c] = *(const float4*)(W + (size_t)(k0 + kk) * 64 + c);
        }
        __syncthreads();
#pragma unroll
        for (int kk = 0; kk < 64; kk += 4) {
            float4 wv0 = *(float4*)&Ws[kk + 0][col4];
            float4 wv1 = *(float4*)&Ws[kk + 1][col4];
            float4 wv2 = *(float4*)&Ws[kk + 2][col4];
            float4 wv3 = *(float4*)&Ws[kk + 3][col4];
#pragma unroll
            for (int r = 0; r < 4; r++) {
                float4 xv = *(float4*)&Xs[row4 + r][kk];
                acc[r][0] += xv.x * wv0.x + xv.y * wv1.x + xv.z * wv2.x + xv.w * wv3.x;
                acc[r][1] += xv.x * wv0.y + xv.y * wv1.y + xv.z * wv2.y + xv.w * wv3.y;
                acc[r][2] += xv.x * wv0.z + xv.y * wv1.z + xv.z * wv2.z + xv.w * wv3.z;
                acc[r][3] += xv.x * wv0.w + xv.y * wv1.w + xv.z * wv2.w + xv.w * wv3.w;
            }
        }
        __syncthreads();
    }
#pragma unroll
    for (int r = 0; r < 4; r++) {
        int row = row0 + row4 + r;
        if (row < n) {
            float4 o = make_float4(acc[r][0], acc[r][1], acc[r][2], acc[r][3]);
            if (BIAS) {
                o.x += bias[col4 + 0]; o.y += bias[col4 + 1];
                o.z += bias[col4 + 2]; o.w += bias[col4 + 3];
            }
            if (RELU) {
                o.x = fmaxf(o.x, 0.f); o.y = fmaxf(o.y, 0.f);
                o.z = fmaxf(o.z, 0.f); o.w = fmaxf(o.w, 0.f);
            }
            if (OUT16) {
                H4 p;
                p.a = __floats2half2_rn(o.x, o.y);
                p.b = __floats2half2_rn(o.z, o.w);
                *(H4*)(out16 + (size_t)row * 64 + col4) = p;
            } else {
                *(float4*)(out + (size_t)row * 64 + col4) = o;
                if (POOL) {
                    int b = __ldg(batch + row);
                    red_add_v4(xg + (size_t)b * 64 + col4, o);
                }
            }
        }
    }
}

// --------- fused middle: z' = relu(U @ W2p + b2p) @ W1_1 -> fp16 ---------
__global__ __launch_bounds__(256, 4) void gemm_mid(const float* __restrict__ U,
                                                   const float* __restrict__ W2p,
                                                   const float* __restrict__ b2p,
                                                   const float* __restrict__ W1_1,
                                                   __half* __restrict__ out16, int n) {
    __shared__ float Xs[64][68];
    __shared__ float Ws[64][64];
    const int tid  = threadIdx.x;
    const int row0 = blockIdx.x * 64;
    const int col4 = (tid & 15) * 4;
    const int row4 = (tid >> 4) * 4;

    float acc[4][4];
#pragma unroll
    for (int r = 0; r < 4; r++)
#pragma unroll
        for (int c = 0; c < 4; c++) acc[r][c] = 0.f;

#pragma unroll
    for (int t = 0; t < 4; t++) {
        int fidx = t * 256 + tid;
        int r = fidx >> 4;
        int c = (fidx & 15) * 4;
        float4 v = make_float4(0.f, 0.f, 0.f, 0.f);
        int row = row0 + r;
        if (row < n) v = *(const float4*)(U + (size_t)row * 64 + c);
        *(float4*)&Xs[r][c] = v;
        *(float4*)&Ws[r][c] = *(const float4*)(W2p + (size_t)r * 64 + c);
    }
    __syncthreads();
#pragma unroll
    for (int kk = 0; kk < 64; kk += 4) {
        float4 wv0 = *(float4*)&Ws[kk + 0][col4];
        float4 wv1 = *(float4*)&Ws[kk + 1][col4];
        float4 wv2 = *(float4*)&Ws[kk + 2][col4];
        float4 wv3 = *(float4*)&Ws[kk + 3][col4];
#pragma unroll
        for (int r = 0; r < 4; r++) {
            float4 xv = *(float4*)&Xs[row4 + r][kk];
            acc[r][0] += xv.x * wv0.x + xv.y * wv1.x + xv.z * wv2.x + xv.w * wv3.x;
            acc[r][1] += xv.x * wv0.y + xv.y * wv1.y + xv.z * wv2.y + xv.w * wv3.y;
            acc[r][2] += xv.x * wv0.z + xv.y * wv1.z + xv.z * wv2.z + xv.w * wv3.z;
            acc[r][3] += xv.x * wv0.w + xv.y * wv1.w + xv.z * wv2.w + xv.w * wv3.w;
        }
    }
    __syncthreads();

    float4 bb = *(const float4*)(b2p + col4);
#pragma unroll
    for (int r = 0; r < 4; r++) {
        float4 h;
        h.x = fmaxf(acc[r][0] + bb.x, 0.f);
        h.y = fmaxf(acc[r][1] + bb.y, 0.f);
        h.z = fmaxf(acc[r][2] + bb.z, 0.f);
        h.w = fmaxf(acc[r][3] + bb.w, 0.f);
        *(float4*)&Xs[row4 + r][col4] = h;
        acc[r][0] = acc[r][1] = acc[r][2] = acc[r][3] = 0.f;
    }
#pragma unroll
    for (int t = 0; t < 4; t++) {
        int fidx = t * 256 + tid;
        int kk = fidx >> 4;
        int c = (fidx & 15) * 4;
        *(float4*)&Ws[kk][c] = *(const float4*)(W1_1 + (size_t)kk * 64 + c);
    }
    __syncthreads();
#pragma unroll
    for (int kk = 0; kk < 64; kk += 4) {
        float4 wv0 = *(float4*)&Ws[kk + 0][col4];
        float4 wv1 = *(float4*)&Ws[kk + 1][col4];
        float4 wv2 = *(float4*)&Ws[kk + 2][col4];
        float4 wv3 = *(float4*)&Ws[kk + 3][col4];
#pragma unroll
        for (int r = 0; r < 4; r++) {
            float4 xv = *(float4*)&Xs[row4 + r][kk];
            acc[r][0] += xv.x * wv0.x + xv.y * wv1.x + xv.z * wv2.x + xv.w * wv3.x;
            acc[r][1] += xv.x * wv0.y + xv.y * wv1.y + xv.z * wv2.y + xv.w * wv3.y;
            acc[r][2] += xv.x * wv0.z + xv.y * wv1.z + xv.z * wv2.z + xv.w * wv3.z;
            acc[r][3] += xv.x * wv0.w + xv.y * wv1.w + xv.z * wv2.w + xv.w * wv3.w;
        }
    }
#pragma unroll
    for (int r = 0; r < 4; r++) {
        int row = row0 + row4 + r;
        if (row < n) {
            H4 p;
            p.a = __floats2half2_rn(acc[r][0], acc[r][1]);
            p.b = __floats2half2_rn(acc[r][2], acc[r][3]);
            *(H4*)(out16 + (size_t)row * 64 + col4) = p;
        }
    }
}

// ---------------- fold BN into W2/b2; re-zero statsP for next use ----------------
__global__ void bn_finalize(const float* __restrict__ gam, const float* __restrict__ be,
                            const float* __restrict__ W2, const float* __restrict__ b2) {
    const int j = threadIdx.x & 63;
    const int q = threadIdx.x >> 6;  // 0..3
    __shared__ float scale[64], shift[64];
    __shared__ float pa[4][64];
    if (q == 0) {
        float sum = 0.f, sq = 0.f;
#pragma unroll 8
        for (int r = 0; r < NREP; r++) {
            sum += g_statsP[r * 128 + j];
            sq  += g_statsP[r * 128 + 64 + j];
        }
        const float inv_n = 1.0f / (float)NN;
        float mu = sum * inv_n;
        float var = sq * inv_n - mu * mu;
        float sc = gam[j] * rsqrtf(var + 1e-5f);
        scale[j] = sc;
        shift[j] = be[j] - mu * sc;
    }
    __syncthreads();
    for (int i = threadIdx.x; i < NREP * 128; i += 256) g_statsP[i] = 0.f;

    float acc = 0.f;
#pragma unroll
    for (int t = 0; t < 16; t++) {
        int k = q * 16 + t;
        float w = W2[k * 64 + j];
        g_W2p[k * 64 + j] = scale[k] * w;
        acc += shift[k] * w;
    }
    pa[q][j] = acc;
    __syncthreads();
    if (q == 0) g_b2p[j] = b2[j] + pa[0][j] + pa[1][j] + pa[2][j] + pa[3][j];
}

extern "C" void kernel_launch(void* const* d_in, const int* in_sizes, int n_in,
                              void* d_out, int out_size) {
    const float* x     = (const float*)d_in[0];
    const int*   ei    = (const int*)d_in[1];
    const int*   batch = (const int*)d_in[2];
    const float* W1_0  = (const float*)d_in[3];
    const float* b1_0  = (const float*)d_in[4];
    const float* g_0   = (const float*)d_in[5];
    const float* be_0  = (const float*)d_in[6];
    const float* W2_0  = (const float*)d_in[7];
    const float* b2_0  = (const float*)d_in[8];
    const float* W1_1  = (const float*)d_in[9];
    const float* b1_1  = (const float*)d_in[10];
    const float* g_1   = (const float*)d_in[11];
    const float* be_1  = (const float*)d_in[12];
    const float* W2_1  = (const float*)d_in[13];
    const float* b2_1  = (const float*)d_in[14];

    const int4* src4 = (const int4*)ei;
    const int4* dst4 = (const int4*)(ei + EE);

    __half* z16;
    float *u, *W2p, *b2p;
    int *cur;
    cudaGetSymbolAddress((void**)&z16, g_z16);
    cudaGetSymbolAddress((void**)&u, g_u);
    cudaGetSymbolAddress((void**)&W2p, g_W2p);
    cudaGetSymbolAddress((void**)&b2p, g_b2p);
    cudaGetSymbolAddress((void**)&cur, g_cur);

    float* out  = (float*)d_out;
    float* xg   = out;            // (G, 64)
    float* hout = out + GG * 64;  // (N, 64)

    const int gemm_blocks  = (NN + 63) / 64;   // 1563
    const int edge4_blocks = (EE / 4 + 255) / 256;
    const int node_blocks  = NN / 8;           // 12500

    // ---------- CSR build (rank-capture) ----------
    cudaMemsetAsync(cur, 0, NN * sizeof(int));
    hist_kernel<<<edge4_blocks, 256>>>(dst4);
    scan_kernel<<<1, 1024>>>(xg);                     // + zero statsP, xg

    // ---------- layer 0 (gemm0 carries the atomic-free scatter tail) ----------
    gemm0_scatter<<<gemm_blocks, 256>>>(x, W1_0, z16, NN, src4, dst4);
    gather_post<<<node_blocks, 256>>>(z16, b1_0, u);
    bn_finalize<<<1, 256>>>(g_0, be_0, W2_0, b2_0);
    gemm_mid<<<gemm_blocks, 256>>>(u, W2p, b2p, W1_1, z16, NN);

    // ---------- layer 1 ----------
    gather_post<<<node_blocks, 256>>>(z16, b1_1, u);
    bn_finalize<<<1, 256>>>(g_1, be_1, W2_1, b2_1);
    gemm64<64, true, true, true, false><<<gemm_blocks, 256>>>(
        u, W2p, b2p, hout, nullptr, NN, batch, xg);
}